// round 11
// baseline (speedup 1.0000x reference)
#include <cuda_runtime.h>
#include <cuda_bf16.h>
#include <cstdint>

// out[b,q,d] = qm[q] * (sum_k km[k]*exp(QK^T/8) V[k,d]) / max(rowsum,1)
// B=8, L=2048, D=64 fp32.
// Pre-pass: split fp32 -> bf16 hi/lo for Q,K,V into global scratch (smem-image layout).
// Main: cp.async double-buffered tiles, ldmatrix.x4 frags, mma.sync bf16 3-term split.

#define SEQ  2048
#define HD   64
#define BQ   128
#define BK   128
#define NKT  (SEQ/BK)
#define RST  144                 // smem row stride bytes (72 bf16) -> conflict-free ldmatrix
#define ARR  18432               // one array (128 rows x 144B) in smem
#define TILE_SM  (4*ARR)         // KH,KL,VH,VL
#define TILE_GL  65536           // 4 arrays x 16384 dense (128B rows) in scratch

#define OFF_KM  0                // 2 x 128 floats
#define OFF_QS  1024             // QH,QL stage: 2*18432 = 36864
#define OFF_T   37888            // 2 tile buffers
#define SMEM_BYTES (OFF_T + 2*TILE_SM)   // 185344

static __device__ __align__(16) unsigned char g_kvsc[8 * 16 * TILE_GL];   // 8.4 MB
static __device__ __align__(16) unsigned char g_qsc [8 * 16 * 2 * 16384]; // 4.2 MB

__device__ __forceinline__ uint32_t smem_u32(const void* p) {
    uint32_t a;
    asm("{ .reg .u64 t; cvta.to.shared.u64 t, %1; cvt.u32.u64 %0, t; }" : "=r"(a) : "l"(p));
    return a;
}
__device__ __forceinline__ uint32_t packbf(float lo, float hi) {
    uint32_t r;
    asm("cvt.rn.bf16x2.f32 %0, %1, %2;" : "=r"(r) : "f"(hi), "f"(lo));
    return r;
}
__device__ __forceinline__ float bflo(uint32_t p) { return __uint_as_float(p << 16); }
__device__ __forceinline__ float bfhi(uint32_t p) { return __uint_as_float(p & 0xffff0000u); }

__device__ __forceinline__ void mma16816(float c[4], const uint32_t a[4], const uint32_t b[2]) {
    asm volatile("mma.sync.aligned.m16n8k16.row.col.f32.bf16.bf16.f32 "
        "{%0,%1,%2,%3}, {%4,%5,%6,%7}, {%8,%9}, {%0,%1,%2,%3};"
        : "+f"(c[0]), "+f"(c[1]), "+f"(c[2]), "+f"(c[3])
        : "r"(a[0]), "r"(a[1]), "r"(a[2]), "r"(a[3]), "r"(b[0]), "r"(b[1]));
}
#define LDMX4(r0,r1,r2,r3,a) \
    asm volatile("ldmatrix.sync.aligned.m8n8.x4.shared.b16 {%0,%1,%2,%3}, [%4];" \
                 : "=r"(r0),"=r"(r1),"=r"(r2),"=r"(r3) : "r"(a))
#define LDMX4T(r0,r1,r2,r3,a) \
    asm volatile("ldmatrix.sync.aligned.m8n8.x4.trans.shared.b16 {%0,%1,%2,%3}, [%4];" \
                 : "=r"(r0),"=r"(r1),"=r"(r2),"=r"(r3) : "r"(a))

__device__ __forceinline__ void cpa(uint32_t dst, const void* src) {
    asm volatile("cp.async.cg.shared.global [%0], [%1], 16;" :: "r"(dst), "l"(src) : "memory");
}
#define CP_COMMIT() asm volatile("cp.async.commit_group;" ::: "memory")
#define CP_WAIT(n)  asm volatile("cp.async.wait_group %0;" :: "n"(n) : "memory")

// ---------------- pre-pass: fp32 -> bf16 hi/lo split into scratch ----------------
__global__ __launch_bounds__(256)
void attn77_prep(const float* __restrict__ Q, const float* __restrict__ K,
                 const float* __restrict__ V)
{
    int idx = blockIdx.x * 256 + threadIdx.x;        // 0 .. 393215
    int t   = idx >> 17;                              // 0=K, 1=V, 2=Q
    int seg = idx & 7, row = (idx >> 3) & 2047, b = (idx >> 14) & 7;
    const float* s = (t == 0 ? K : (t == 1 ? V : Q)) + ((size_t)(b * 2048 + row)) * 64 + seg * 8;
    float4 v0 = *(const float4*)s, v1 = *(const float4*)(s + 4);
    uint4 hi, lo;
    hi.x = packbf(v0.x, v0.y); hi.y = packbf(v0.z, v0.w);
    hi.z = packbf(v1.x, v1.y); hi.w = packbf(v1.z, v1.w);
    lo.x = packbf(v0.x - bflo(hi.x), v0.y - bfhi(hi.x));
    lo.y = packbf(v0.z - bflo(hi.y), v0.w - bfhi(hi.y));
    lo.z = packbf(v1.x - bflo(hi.z), v1.y - bfhi(hi.z));
    lo.w = packbf(v1.z - bflo(hi.w), v1.w - bfhi(hi.w));
    int kt = row >> 7, r = row & 127;
    unsigned char* d;
    if (t < 2) d = g_kvsc + ((size_t)((b * 16 + kt) * 4 + (t ? 2 : 0)) << 14) + r * 128 + seg * 16;
    else       d = g_qsc  + ((size_t)((b * 16 + kt) * 2) << 14)               + r * 128 + seg * 16;
    *(uint4*)d = hi;
    *(uint4*)(d + 16384) = lo;   // lo array immediately follows hi
}

// ---------------- main kernel ----------------
__device__ __forceinline__ void prefetch_tile(uint32_t dstb, const unsigned char* src, int tid) {
    #pragma unroll
    for (int j = 0; j < 16; j++) {
        int c = tid + j * 256;                 // 4096 x 16B chunks
        int a = c >> 10, rc = c & 1023;
        uint32_t dst = dstb + a * ARR + (rc >> 3) * RST + (rc & 7) * 16;
        cpa(dst, src + c * 16);
    }
}

__global__ __launch_bounds__(256, 1)
void attn77_mma(const int* __restrict__ QM, const int* __restrict__ KM,
                float* __restrict__ O)
{
    extern __shared__ char smem[];
    const uint32_t sb = smem_u32(smem);
    float* kms0 = (float*)(smem + OFF_KM);

    const int tid  = threadIdx.x;
    const int wid  = tid >> 5, lane = tid & 31;
    const int g    = lane >> 2, t = lane & 3;
    const int b    = blockIdx.x >> 4;
    const int q0   = (blockIdx.x & 15) * BQ;
    const int r0   = wid * 16;

    const unsigned char* tsrc = g_kvsc + ((size_t)(b * 16) * TILE_GL);
    const unsigned char* qsrc = g_qsc  + ((size_t)blockIdx.x << 15);

    // ---- prologue: prefetch Q stage, tile0, tile1; load k-masks 0/1 ----
    #pragma unroll
    for (int j = 0; j < 8; j++) {
        int c = tid + j * 256;                 // 2048 chunks (QH then QL)
        uint32_t dst = sb + OFF_QS + (c >> 10) * ARR + ((c >> 3) & 127) * RST + (c & 7) * 16;
        cpa(dst, qsrc + c * 16);
    }
    CP_COMMIT();
    prefetch_tile(sb + OFF_T,           tsrc,           tid); CP_COMMIT();
    prefetch_tile(sb + OFF_T + TILE_SM, tsrc + TILE_GL, tid); CP_COMMIT();
    if (tid < 128) {
        kms0[tid]       = (float)KM[b * SEQ + tid];
        kms0[128 + tid] = (float)KM[b * SEQ + 128 + tid];
    }

    // ---- build Q fragments (A-frags) from the stage ----
    CP_WAIT(2);
    __syncthreads();
    uint32_t qh[4][4], ql[4][4];
    {
        const uint32_t aoff = (uint32_t)((lane & 15) * RST + ((lane >> 4) << 4));
        #pragma unroll
        for (int ks = 0; ks < 4; ks++) {
            uint32_t a = sb + OFF_QS + (uint32_t)(r0 * RST + 32 * ks) + aoff;
            LDMX4(qh[ks][0], qh[ks][1], qh[ks][2], qh[ks][3], a);
            LDMX4(ql[ks][0], ql[ks][1], ql[ks][2], ql[ks][3], a + ARR);
        }
    }

    float o[8][4];
    #pragma unroll
    for (int i = 0; i < 8; i++) { o[i][0] = o[i][1] = o[i][2] = o[i][3] = 0.f; }
    float rs0 = 0.f, rs1 = 0.f;

    const uint32_t koff = (uint32_t)(((lane & 7) + ((lane >> 4) << 3)) * RST + ((lane & 8) << 1));
    const uint32_t voff = (uint32_t)((lane & 15) * RST + ((lane >> 4) << 4));

    for (int kt = 0; kt < NKT; kt++) {
        const int cur = kt & 1;
        const uint32_t bK = sb + OFF_T + cur * TILE_SM;   // KH (KL=+ARR, VH=+2ARR, VL=+3ARR)
        const uint32_t bV = bK + 2 * ARR;
        const float* kms = kms0 + cur * 128;

        CP_WAIT(1);
        __syncthreads();

        // ---- MMA1: S = Qhi*Khi + Qhi*Klo + Qlo*Khi ----
        float s[16][4];
        #pragma unroll
        for (int i = 0; i < 16; i++) { s[i][0] = s[i][1] = s[i][2] = s[i][3] = 0.f; }

        #pragma unroll
        for (int ks = 0; ks < 4; ks++) {
            #pragma unroll
            for (int h = 0; h < 2; h++) {
                uint32_t kh[8][2], kl[8][2];
                #pragma unroll
                for (int g4 = 0; g4 < 4; g4++) {
                    uint32_t a = bK + (uint32_t)((h * 64 + 16 * g4) * RST + 32 * ks) + koff;
                    LDMX4(kh[2*g4][0], kh[2*g4][1], kh[2*g4+1][0], kh[2*g4+1][1], a);
                    LDMX4(kl[2*g4][0], kl[2*g4][1], kl[2*g4+1][0], kl[2*g4+1][1], a + ARR);
                }
                #pragma unroll
                for (int n = 0; n < 8; n++) mma16816(s[8*h+n], qh[ks], kh[n]);
                #pragma unroll
                for (int n = 0; n < 8; n++) mma16816(s[8*h+n], qh[ks], kl[n]);
                #pragma unroll
                for (int n = 0; n < 8; n++) mma16816(s[8*h+n], ql[ks], kh[n]);
            }
        }

        // ---- exp + mask + rowsum + P split; MMA2: O += P*V (3-term) ----
        #pragma unroll
        for (int kk = 0; kk < 8; kk++) {
            uint32_t pa[4], pl[4];
            #pragma unroll
            for (int jj = 0; jj < 2; jj++) {
                int j = 2 * kk + jj;
                float2 km2 = *(const float2*)(kms + 8 * j + 2 * t);
                float e0 = km2.x * __expf(s[j][0] * 0.125f);
                float e1 = km2.y * __expf(s[j][1] * 0.125f);
                float e2 = km2.x * __expf(s[j][2] * 0.125f);
                float e3 = km2.y * __expf(s[j][3] * 0.125f);
                rs0 += e0 + e1;
                rs1 += e2 + e3;
                uint32_t h01 = packbf(e0, e1), h23 = packbf(e2, e3);
                pa[2*jj]     = h01;
                pa[2*jj + 1] = h23;
                pl[2*jj]     = packbf(e0 - bflo(h01), e1 - bfhi(h01));
                pl[2*jj + 1] = packbf(e2 - bflo(h23), e3 - bfhi(h23));
            }
            uint32_t vh[8][2], vl[8][2];
            #pragma unroll
            for (int g4 = 0; g4 < 4; g4++) {
                uint32_t a = bV + (uint32_t)((16 * kk) * RST + 32 * g4) + voff;
                LDMX4T(vh[2*g4][0], vh[2*g4][1], vh[2*g4+1][0], vh[2*g4+1][1], a);
                LDMX4T(vl[2*g4][0], vl[2*g4][1], vl[2*g4+1][0], vl[2*g4+1][1], a + ARR);
            }
            #pragma unroll
            for (int dn = 0; dn < 8; dn++) mma16816(o[dn], pa, vh[dn]);
            #pragma unroll
            for (int dn = 0; dn < 8; dn++) mma16816(o[dn], pa, vl[dn]);
            #pragma unroll
            for (int dn = 0; dn < 8; dn++) mma16816(o[dn], pl, vh[dn]);
        }

        __syncthreads();   // all reads of buf[cur] done
        // ---- prefetch tile kt+2 into buf[cur] ----
        if (kt + 2 < NKT) {
            prefetch_tile(sb + OFF_T + cur * TILE_SM, tsrc + (size_t)(kt + 2) * TILE_GL, tid);
            if (tid < 128) kms0[cur * 128 + tid] = (float)KM[b * SEQ + (kt + 2) * 128 + tid];
        }
        CP_COMMIT();       // empty group near the tail keeps wait counts aligned
    }

    // ---- rowsum reduce within quad ----
    rs0 += __shfl_xor_sync(0xffffffffu, rs0, 1);
    rs0 += __shfl_xor_sync(0xffffffffu, rs0, 2);
    rs1 += __shfl_xor_sync(0xffffffffu, rs1, 1);
    rs1 += __shfl_xor_sync(0xffffffffu, rs1, 2);

    const int row0 = q0 + r0 + g, row1 = row0 + 8;
    const float inv0 = (float)QM[b * SEQ + row0] / fmaxf(rs0, 1.0f);
    const float inv1 = (float)QM[b * SEQ + row1] / fmaxf(rs1, 1.0f);

    float* Ob = O + (size_t)b * SEQ * HD;
    #pragma unroll
    for (int dn = 0; dn < 8; dn++) {
        float2 w0; w0.x = o[dn][0] * inv0; w0.y = o[dn][1] * inv0;
        *(float2*)(Ob + (size_t)row0 * HD + 8 * dn + 2 * t) = w0;
        float2 w1; w1.x = o[dn][2] * inv1; w1.y = o[dn][3] * inv1;
        *(float2*)(Ob + (size_t)row1 * HD + 8 * dn + 2 * t) = w1;
    }
}

extern "C" void kernel_launch(void* const* d_in, const int* in_sizes, int n_in,
                              void* d_out, int out_size)
{
    const float* Q  = (const float*)d_in[0];
    const float* K  = (const float*)d_in[1];
    const float* V  = (const float*)d_in[2];
    const int*   QM = (const int*)d_in[3];
    const int*   KM = (const int*)d_in[4];
    float*       O  = (float*)d_out;

    attn77_prep<<<1536, 256>>>(Q, K, V);

    cudaFuncSetAttribute(attn77_mma, cudaFuncAttributeMaxDynamicSharedMemorySize, SMEM_BYTES);
    attn77_mma<<<128, 256, SMEM_BYTES>>>(QM, KM, O);
}

// round 13
// speedup vs baseline: 1.0004x; 1.0004x over previous
#include <cuda_runtime.h>
#include <cuda_bf16.h>
#include <cstdint>

// out[b,q,d] = qm[q] * (sum_k km[k]*exp(QK^T/8) V[k,d]) / max(rowsum,1)
// B=8, L=2048, D=64 fp32.
// Pre-pass: split fp32 -> bf16 hi/lo for Q,K,V into global scratch (smem-image layout).
// Main: 512-thread CTA (16 warps, 4/SMSP). Warp-halves split the N/k dimension:
// warps 0-7 handle S cols / k rows [0,64), warps 8-15 handle [64,128).
// cp.async double-buffered tiles, ldmatrix.x4 frags, mma.sync bf16 3-term split.

#define SEQ  2048
#define HD   64
#define BQ   128
#define BK   128
#define NKT  (SEQ/BK)
#define RST  144                 // smem row stride bytes (72 bf16) -> conflict-free ldmatrix
#define ARR  18432               // one array (128 rows x 144B) in smem
#define TILE_SM  (4*ARR)         // KH,KL,VH,VL
#define TILE_GL  65536           // 4 arrays x 16384 dense (128B rows) in scratch

#define OFF_KM  0                // 2 x 128 floats
#define OFF_QS  1024             // QH,QL stage: 2*18432 = 36864
#define OFF_T   37888            // 2 tile buffers
#define SMEM_BYTES (OFF_T + 2*TILE_SM)   // 185344
#define RED_ST  68               // reduction row stride (floats)

static __device__ __align__(16) unsigned char g_kvsc[8 * 16 * TILE_GL];   // 8.4 MB
static __device__ __align__(16) unsigned char g_qsc [8 * 16 * 2 * 16384]; // 4.2 MB

__device__ __forceinline__ uint32_t smem_u32(const void* p) {
    uint32_t a;
    asm("{ .reg .u64 t; cvta.to.shared.u64 t, %1; cvt.u32.u64 %0, t; }" : "=r"(a) : "l"(p));
    return a;
}
__device__ __forceinline__ uint32_t packbf(float lo, float hi) {
    uint32_t r;
    asm("cvt.rn.bf16x2.f32 %0, %1, %2;" : "=r"(r) : "f"(hi), "f"(lo));
    return r;
}
__device__ __forceinline__ float bflo(uint32_t p) { return __uint_as_float(p << 16); }
__device__ __forceinline__ float bfhi(uint32_t p) { return __uint_as_float(p & 0xffff0000u); }

__device__ __forceinline__ void mma16816(float c[4], const uint32_t a[4], const uint32_t b[2]) {
    asm volatile("mma.sync.aligned.m16n8k16.row.col.f32.bf16.bf16.f32 "
        "{%0,%1,%2,%3}, {%4,%5,%6,%7}, {%8,%9}, {%0,%1,%2,%3};"
        : "+f"(c[0]), "+f"(c[1]), "+f"(c[2]), "+f"(c[3])
        : "r"(a[0]), "r"(a[1]), "r"(a[2]), "r"(a[3]), "r"(b[0]), "r"(b[1]));
}
#define LDMX4(r0,r1,r2,r3,a) \
    asm volatile("ldmatrix.sync.aligned.m8n8.x4.shared.b16 {%0,%1,%2,%3}, [%4];" \
                 : "=r"(r0),"=r"(r1),"=r"(r2),"=r"(r3) : "r"(a))
#define LDMX4T(r0,r1,r2,r3,a) \
    asm volatile("ldmatrix.sync.aligned.m8n8.x4.trans.shared.b16 {%0,%1,%2,%3}, [%4];" \
                 : "=r"(r0),"=r"(r1),"=r"(r2),"=r"(r3) : "r"(a))

__device__ __forceinline__ void cpa(uint32_t dst, const void* src) {
    asm volatile("cp.async.cg.shared.global [%0], [%1], 16;" :: "r"(dst), "l"(src) : "memory");
}
#define CP_COMMIT() asm volatile("cp.async.commit_group;" ::: "memory")
#define CP_WAIT(n)  asm volatile("cp.async.wait_group %0;" :: "n"(n) : "memory")

// ---------------- pre-pass: fp32 -> bf16 hi/lo split into scratch ----------------
__global__ __launch_bounds__(256)
void attn77_prep(const float* __restrict__ Q, const float* __restrict__ K,
                 const float* __restrict__ V)
{
    int idx = blockIdx.x * 256 + threadIdx.x;        // 0 .. 393215
    int t   = idx >> 17;                              // 0=K, 1=V, 2=Q
    int seg = idx & 7, row = (idx >> 3) & 2047, b = (idx >> 14) & 7;
    const float* s = (t == 0 ? K : (t == 1 ? V : Q)) + ((size_t)(b * 2048 + row)) * 64 + seg * 8;
    float4 v0 = *(const float4*)s, v1 = *(const float4*)(s + 4);
    uint4 hi, lo;
    hi.x = packbf(v0.x, v0.y); hi.y = packbf(v0.z, v0.w);
    hi.z = packbf(v1.x, v1.y); hi.w = packbf(v1.z, v1.w);
    lo.x = packbf(v0.x - bflo(hi.x), v0.y - bfhi(hi.x));
    lo.y = packbf(v0.z - bflo(hi.y), v0.w - bfhi(hi.y));
    lo.z = packbf(v1.x - bflo(hi.z), v1.y - bfhi(hi.z));
    lo.w = packbf(v1.z - bflo(hi.w), v1.w - bfhi(hi.w));
    int kt = row >> 7, r = row & 127;
    unsigned char* d;
    if (t < 2) d = g_kvsc + ((size_t)((b * 16 + kt) * 4 + (t ? 2 : 0)) << 14) + r * 128 + seg * 16;
    else       d = g_qsc  + ((size_t)((b * 16 + kt) * 2) << 14)               + r * 128 + seg * 16;
    *(uint4*)d = hi;
    *(uint4*)(d + 16384) = lo;
}

// ---------------- main kernel ----------------
__device__ __forceinline__ void prefetch_tile(uint32_t dstb, const unsigned char* src, int tid) {
    #pragma unroll
    for (int j = 0; j < 8; j++) {
        int c = tid + j * 512;                 // 4096 x 16B chunks
        int a = c >> 10, rc = c & 1023;
        uint32_t dst = dstb + a * ARR + (rc >> 3) * RST + (rc & 7) * 16;
        cpa(dst, src + c * 16);
    }
}

__global__ __launch_bounds__(512, 1)
void attn77_mma(const int* __restrict__ QM, const int* __restrict__ KM,
                float* __restrict__ O)
{
    extern __shared__ char smem[];
    const uint32_t sb = smem_u32(smem);
    float* kms0 = (float*)(smem + OFF_KM);

    const int tid  = threadIdx.x;
    const int wid  = tid >> 5, lane = tid & 31;
    const int g    = lane >> 2, t = lane & 3;
    const int mw   = wid & 7;                 // m-tile index (16 q rows)
    const int nh   = wid >> 3;                // column/k half (0 or 1)
    const int b    = blockIdx.x >> 4;
    const int q0   = (blockIdx.x & 15) * BQ;
    const int r0   = mw * 16;

    const unsigned char* tsrc = g_kvsc + ((size_t)(b * 16) * TILE_GL);
    const unsigned char* qsrc = g_qsc  + ((size_t)blockIdx.x << 15);

    // ---- prologue: prefetch Q stage, tile0, tile1; load k-masks 0/1 ----
    #pragma unroll
    for (int j = 0; j < 4; j++) {
        int c = tid + j * 512;                 // 2048 chunks (QH then QL)
        uint32_t dst = sb + OFF_QS + (c >> 10) * ARR + ((c >> 3) & 127) * RST + (c & 7) * 16;
        cpa(dst, qsrc + c * 16);
    }
    CP_COMMIT();
    prefetch_tile(sb + OFF_T,           tsrc,           tid); CP_COMMIT();
    prefetch_tile(sb + OFF_T + TILE_SM, tsrc + TILE_GL, tid); CP_COMMIT();
    if (tid < 128) {
        kms0[tid]       = (float)KM[b * SEQ + tid];
        kms0[128 + tid] = (float)KM[b * SEQ + 128 + tid];
    }

    CP_WAIT(2);            // Q stage resident
    __syncthreads();

    float o[8][4];
    #pragma unroll
    for (int i = 0; i < 8; i++) { o[i][0] = o[i][1] = o[i][2] = o[i][3] = 0.f; }
    float rs0 = 0.f, rs1 = 0.f;

    const uint32_t aoff = (uint32_t)((lane & 15) * RST + ((lane >> 4) << 4));
    const uint32_t koff = (uint32_t)(((lane & 7) + ((lane >> 4) << 3)) * RST + ((lane & 8) << 1));
    const uint32_t voff = (uint32_t)((lane & 15) * RST + ((lane >> 4) << 4));
    const uint32_t qbase = sb + OFF_QS + (uint32_t)(r0 * RST) + aoff;

    for (int kt = 0; kt < NKT; kt++) {
        const int cur = kt & 1;
        const uint32_t bK = sb + OFF_T + cur * TILE_SM + (uint32_t)(nh * 64 * RST);
        const uint32_t bV = sb + OFF_T + cur * TILE_SM + 2 * ARR + (uint32_t)(nh * 64 * RST);
        const float* kms = kms0 + cur * 128 + nh * 64;

        CP_WAIT(1);
        __syncthreads();

        // ---- MMA1: S(half) = Qhi*Khi + Qhi*Klo + Qlo*Khi ----
        float s[8][4];
        #pragma unroll
        for (int i = 0; i < 8; i++) { s[i][0] = s[i][1] = s[i][2] = s[i][3] = 0.f; }

        #pragma unroll
        for (int ks = 0; ks < 4; ks++) {
            uint32_t qh[4], ql[4];
            uint32_t qa = qbase + 32u * ks;
            LDMX4(qh[0], qh[1], qh[2], qh[3], qa);
            LDMX4(ql[0], ql[1], ql[2], ql[3], qa + ARR);
            uint32_t kh[8][2], kl[8][2];
            #pragma unroll
            for (int g4 = 0; g4 < 4; g4++) {
                uint32_t a = bK + (uint32_t)(16 * g4 * RST + 32 * ks) + koff;
                LDMX4(kh[2*g4][0], kh[2*g4][1], kh[2*g4+1][0], kh[2*g4+1][1], a);
                LDMX4(kl[2*g4][0], kl[2*g4][1], kl[2*g4+1][0], kl[2*g4+1][1], a + ARR);
            }
            #pragma unroll
            for (int n = 0; n < 8; n++) mma16816(s[n], qh, kh[n]);
            #pragma unroll
            for (int n = 0; n < 8; n++) mma16816(s[n], qh, kl[n]);
            #pragma unroll
            for (int n = 0; n < 8; n++) mma16816(s[n], ql, kh[n]);
        }

        // ---- exp + mask + rowsum + P split; MMA2 over this warp's k-half ----
        #pragma unroll
        for (int kk = 0; kk < 4; kk++) {
            uint32_t pa[4], pl[4];
            #pragma unroll
            for (int jj = 0; jj < 2; jj++) {
                int j = 2 * kk + jj;
                float2 km2 = *(const float2*)(kms + 8 * j + 2 * t);
                float e0 = km2.x * __expf(s[j][0] * 0.125f);
                float e1 = km2.y * __expf(s[j][1] * 0.125f);
                float e2 = km2.x * __expf(s[j][2] * 0.125f);
                float e3 = km2.y * __expf(s[j][3] * 0.125f);
                rs0 += e0 + e1;
                rs1 += e2 + e3;
                uint32_t h01 = packbf(e0, e1), h23 = packbf(e2, e3);
                pa[2*jj]     = h01;
                pa[2*jj + 1] = h23;
                pl[2*jj]     = packbf(e0 - bflo(h01), e1 - bfhi(h01));
                pl[2*jj + 1] = packbf(e2 - bflo(h23), e3 - bfhi(h23));
            }
            uint32_t vh[8][2], vl[8][2];
            #pragma unroll
            for (int g4 = 0; g4 < 4; g4++) {
                uint32_t a = bV + (uint32_t)((16 * kk) * RST + 32 * g4) + voff;
                LDMX4T(vh[2*g4][0], vh[2*g4][1], vh[2*g4+1][0], vh[2*g4+1][1], a);
                LDMX4T(vl[2*g4][0], vl[2*g4][1], vl[2*g4+1][0], vl[2*g4+1][1], a + ARR);
            }
            #pragma unroll
            for (int dn = 0; dn < 8; dn++) mma16816(o[dn], pa, vh[dn]);
            #pragma unroll
            for (int dn = 0; dn < 8; dn++) mma16816(o[dn], pa, vl[dn]);
            #pragma unroll
            for (int dn = 0; dn < 8; dn++) mma16816(o[dn], pl, vh[dn]);
        }

        __syncthreads();   // all reads of buf[cur] done
        if (kt + 2 < NKT) {
            prefetch_tile(sb + OFF_T + cur * TILE_SM, tsrc + (size_t)(kt + 2) * TILE_GL, tid);
            if (tid < 128) kms0[cur * 128 + tid] = (float)KM[b * SEQ + (kt + 2) * 128 + tid];
        }
        CP_COMMIT();
    }

    // ---- rowsum reduce within quad ----
    rs0 += __shfl_xor_sync(0xffffffffu, rs0, 1);
    rs0 += __shfl_xor_sync(0xffffffffu, rs0, 2);
    rs1 += __shfl_xor_sync(0xffffffffu, rs1, 1);
    rs1 += __shfl_xor_sync(0xffffffffu, rs1, 2);

    // ---- cross-half reduction (nh=1 stores, nh=0 adds and writes) ----
    float* redo = (float*)(smem + OFF_T);                     // [128][RED_ST]
    float* reds = (float*)(smem + OFF_T + 128 * RED_ST * 4);  // [128]
    __syncthreads();        // tile buffers no longer needed; safe to reuse

    if (nh == 1) {
        #pragma unroll
        for (int dn = 0; dn < 8; dn++) {
            float2 w0; w0.x = o[dn][0]; w0.y = o[dn][1];
            *(float2*)(&redo[(r0 + g) * RED_ST + 8 * dn + 2 * t]) = w0;
            float2 w1; w1.x = o[dn][2]; w1.y = o[dn][3];
            *(float2*)(&redo[(r0 + g + 8) * RED_ST + 8 * dn + 2 * t]) = w1;
        }
        if (t == 0) { reds[r0 + g] = rs0; reds[r0 + g + 8] = rs1; }
    }
    __syncthreads();

    if (nh == 0) {
        const int row0 = q0 + r0 + g, row1 = row0 + 8;
        const float tot0 = rs0 + reds[r0 + g];
        const float tot1 = rs1 + reds[r0 + g + 8];
        const float inv0 = (float)QM[b * SEQ + row0] / fmaxf(tot0, 1.0f);
        const float inv1 = (float)QM[b * SEQ + row1] / fmaxf(tot1, 1.0f);
        float* Ob = O + (size_t)b * SEQ * HD;
        #pragma unroll
        for (int dn = 0; dn < 8; dn++) {
            float2 p0 = *(const float2*)(&redo[(r0 + g) * RED_ST + 8 * dn + 2 * t]);
            float2 p1 = *(const float2*)(&redo[(r0 + g + 8) * RED_ST + 8 * dn + 2 * t]);
            float2 w0; w0.x = (o[dn][0] + p0.x) * inv0; w0.y = (o[dn][1] + p0.y) * inv0;
            *(float2*)(Ob + (size_t)row0 * HD + 8 * dn + 2 * t) = w0;
            float2 w1; w1.x = (o[dn][2] + p1.x) * inv1; w1.y = (o[dn][3] + p1.y) * inv1;
            *(float2*)(Ob + (size_t)row1 * HD + 8 * dn + 2 * t) = w1;
        }
    }
}

extern "C" void kernel_launch(void* const* d_in, const int* in_sizes, int n_in,
                              void* d_out, int out_size)
{
    const float* Q  = (const float*)d_in[0];
    const float* K  = (const float*)d_in[1];
    const float* V  = (const float*)d_in[2];
    const int*   QM = (const int*)d_in[3];
    const int*   KM = (const int*)d_in[4];
    float*       O  = (float*)d_out;

    attn77_prep<<<1536, 256>>>(Q, K, V);

    cudaFuncSetAttribute(attn77_mma, cudaFuncAttributeMaxDynamicSharedMemorySize, SMEM_BYTES);
    attn77_mma<<<128, 512, SMEM_BYTES>>>(QM, KM, O);
}

// round 14
// speedup vs baseline: 1.9000x; 1.8993x over previous
#include <cuda_runtime.h>
#include <cuda_fp16.h>
#include <cstdint>

// out[b,q,d] = qm[q] * (sum_k km[k]*exp(QK^T/8) V[k,d]) / max(rowsum,1)
// B=8, L=2048, D=64 fp32.
// Pre-pass: convert Q(,pre-scaled by 1/8),K,V fp32 -> fp16 into global scratch.
// Main: 512-thread CTA, warp-halves split k/N dim, cp.async double-buffered
// tiles, ldmatrix.x4, single-term fp16 mma.sync (fp32 accum).
// Rowsum uses the fp16-rounded P values (consistent with MMA2 numerator).

#define SEQ  2048
#define HD   64
#define BQ   128
#define BK   128
#define NKT  (SEQ/BK)
#define RST  144                 // smem row stride bytes (64 fp16 + 16B pad)
#define ARR  18432               // one array (128 rows x 144B) in smem
#define TILE_SM  (2*ARR)         // K,V
#define TILE_GL  32768           // K(16KB)+V(16KB) dense in scratch

#define OFF_KM  0                // 2 x 128 floats
#define OFF_QS  1024             // Q stage: 18432
#define OFF_T   19456            // 2 tile buffers
#define SMEM_BYTES (OFF_T + 2*TILE_SM)   // 93184
#define RED_ST  68               // reduction row stride (floats)

static __device__ __align__(16) unsigned char g_kvsc[8 * 16 * TILE_GL];   // 4.2 MB
static __device__ __align__(16) unsigned char g_qsc [8 * 16 * 16384];     // 2.1 MB

__device__ __forceinline__ uint32_t smem_u32(const void* p) {
    uint32_t a;
    asm("{ .reg .u64 t; cvta.to.shared.u64 t, %1; cvt.u32.u64 %0, t; }" : "=r"(a) : "l"(p));
    return a;
}
__device__ __forceinline__ uint32_t packh(float lo, float hi) {
    uint32_t r;
    asm("cvt.rn.f16x2.f32 %0, %1, %2;" : "=r"(r) : "f"(hi), "f"(lo));
    return r;
}
__device__ __forceinline__ float2 unph(uint32_t h) {
    __half2 v = *reinterpret_cast<__half2*>(&h);
    return __half22float2(v);            // .x = low half
}

__device__ __forceinline__ void mma16816h(float c[4], const uint32_t a[4], const uint32_t b[2]) {
    asm volatile("mma.sync.aligned.m16n8k16.row.col.f32.f16.f16.f32 "
        "{%0,%1,%2,%3}, {%4,%5,%6,%7}, {%8,%9}, {%0,%1,%2,%3};"
        : "+f"(c[0]), "+f"(c[1]), "+f"(c[2]), "+f"(c[3])
        : "r"(a[0]), "r"(a[1]), "r"(a[2]), "r"(a[3]), "r"(b[0]), "r"(b[1]));
}
#define LDMX4(r0,r1,r2,r3,a) \
    asm volatile("ldmatrix.sync.aligned.m8n8.x4.shared.b16 {%0,%1,%2,%3}, [%4];" \
                 : "=r"(r0),"=r"(r1),"=r"(r2),"=r"(r3) : "r"(a))
#define LDMX4T(r0,r1,r2,r3,a) \
    asm volatile("ldmatrix.sync.aligned.m8n8.x4.trans.shared.b16 {%0,%1,%2,%3}, [%4];" \
                 : "=r"(r0),"=r"(r1),"=r"(r2),"=r"(r3) : "r"(a))

__device__ __forceinline__ void cpa(uint32_t dst, const void* src) {
    asm volatile("cp.async.cg.shared.global [%0], [%1], 16;" :: "r"(dst), "l"(src) : "memory");
}
#define CP_COMMIT() asm volatile("cp.async.commit_group;" ::: "memory")
#define CP_WAIT(n)  asm volatile("cp.async.wait_group %0;" :: "n"(n) : "memory")

// ---------------- pre-pass: fp32 -> fp16 into scratch (Q pre-scaled by 1/8) ----------------
__global__ __launch_bounds__(256)
void attn77_prep(const float* __restrict__ Q, const float* __restrict__ K,
                 const float* __restrict__ V)
{
    int idx = blockIdx.x * 256 + threadIdx.x;        // 0 .. 393215
    int t   = idx >> 17;                              // 0=K, 1=V, 2=Q
    int seg = idx & 7, row = (idx >> 3) & 2047, b = (idx >> 14) & 7;
    const float* s = (t == 0 ? K : (t == 1 ? V : Q)) + ((size_t)(b * 2048 + row)) * 64 + seg * 8;
    float4 v0 = *(const float4*)s, v1 = *(const float4*)(s + 4);
    if (t == 2) {                                     // fold 1/sqrt(64) into Q
        v0.x *= 0.125f; v0.y *= 0.125f; v0.z *= 0.125f; v0.w *= 0.125f;
        v1.x *= 0.125f; v1.y *= 0.125f; v1.z *= 0.125f; v1.w *= 0.125f;
    }
    uint4 h;
    h.x = packh(v0.x, v0.y); h.y = packh(v0.z, v0.w);
    h.z = packh(v1.x, v1.y); h.w = packh(v1.z, v1.w);
    int kt = row >> 7, r = row & 127;
    unsigned char* d;
    if (t < 2) d = g_kvsc + (size_t)(b * 16 + kt) * TILE_GL + t * 16384 + r * 128 + seg * 16;
    else       d = g_qsc  + ((size_t)(b * 16 + kt) << 14)                + r * 128 + seg * 16;
    *(uint4*)d = h;
}

// ---------------- main kernel ----------------
__device__ __forceinline__ void prefetch_tile(uint32_t dstb, const unsigned char* src, int tid) {
    #pragma unroll
    for (int j = 0; j < 4; j++) {
        int c = tid + j * 512;                 // 2048 x 16B chunks
        int a = c >> 10, rc = c & 1023;
        uint32_t dst = dstb + a * ARR + (rc >> 3) * RST + (rc & 7) * 16;
        cpa(dst, src + c * 16);
    }
}

__global__ __launch_bounds__(512, 1)
void attn77_mma(const int* __restrict__ QM, const int* __restrict__ KM,
                float* __restrict__ O)
{
    extern __shared__ char smem[];
    const uint32_t sb = smem_u32(smem);
    float* kms0 = (float*)(smem + OFF_KM);

    const int tid  = threadIdx.x;
    const int wid  = tid >> 5, lane = tid & 31;
    const int g    = lane >> 2, t = lane & 3;
    const int mw   = wid & 7;                 // m-tile index (16 q rows)
    const int nh   = wid >> 3;                // column/k half (0 or 1)
    const int b    = blockIdx.x >> 4;
    const int q0   = (blockIdx.x & 15) * BQ;
    const int r0   = mw * 16;

    const unsigned char* tsrc = g_kvsc + ((size_t)(b * 16) * TILE_GL);
    const unsigned char* qsrc = g_qsc  + ((size_t)blockIdx.x << 14);

    // ---- prologue: prefetch Q stage, tile0, tile1; load k-masks 0/1 ----
    #pragma unroll
    for (int j = 0; j < 2; j++) {
        int c = tid + j * 512;                 // 1024 chunks
        uint32_t dst = sb + OFF_QS + (c >> 3) * RST + (c & 7) * 16;
        cpa(dst, qsrc + c * 16);
    }
    CP_COMMIT();
    prefetch_tile(sb + OFF_T,           tsrc,           tid); CP_COMMIT();
    prefetch_tile(sb + OFF_T + TILE_SM, tsrc + TILE_GL, tid); CP_COMMIT();
    if (tid < 128) {
        kms0[tid]       = (float)KM[b * SEQ + tid];
        kms0[128 + tid] = (float)KM[b * SEQ + 128 + tid];
    }

    CP_WAIT(2);            // Q stage resident
    __syncthreads();

    float o[8][4];
    #pragma unroll
    for (int i = 0; i < 8; i++) { o[i][0] = o[i][1] = o[i][2] = o[i][3] = 0.f; }
    float rs0 = 0.f, rs1 = 0.f;

    const uint32_t aoff = (uint32_t)((lane & 15) * RST + ((lane >> 4) << 4));
    const uint32_t koff = (uint32_t)(((lane & 7) + ((lane >> 4) << 3)) * RST + ((lane & 8) << 1));
    const uint32_t voff = (uint32_t)((lane & 15) * RST + ((lane >> 4) << 4));
    const uint32_t qbase = sb + OFF_QS + (uint32_t)(r0 * RST) + aoff;

    for (int kt = 0; kt < NKT; kt++) {
        const int cur = kt & 1;
        const uint32_t bK = sb + OFF_T + cur * TILE_SM + (uint32_t)(nh * 64 * RST);
        const uint32_t bV = sb + OFF_T + cur * TILE_SM + ARR + (uint32_t)(nh * 64 * RST);
        const float* kms = kms0 + cur * 128 + nh * 64;

        CP_WAIT(1);
        __syncthreads();

        // ---- MMA1: S(half) = Q.K^T (single-term fp16) ----
        float s[8][4];
        #pragma unroll
        for (int i = 0; i < 8; i++) { s[i][0] = s[i][1] = s[i][2] = s[i][3] = 0.f; }

        #pragma unroll
        for (int ks = 0; ks < 4; ks++) {
            uint32_t qf[4];
            LDMX4(qf[0], qf[1], qf[2], qf[3], qbase + 32u * ks);
            uint32_t kf[8][2];
            #pragma unroll
            for (int g4 = 0; g4 < 4; g4++) {
                uint32_t a = bK + (uint32_t)(16 * g4 * RST + 32 * ks) + koff;
                LDMX4(kf[2*g4][0], kf[2*g4][1], kf[2*g4+1][0], kf[2*g4+1][1], a);
            }
            #pragma unroll
            for (int n = 0; n < 8; n++) mma16816h(s[n], qf, kf[n]);
        }

        // ---- exp + mask; rowsum from fp16-rounded P; MMA2 single-term ----
        #pragma unroll
        for (int kk = 0; kk < 4; kk++) {
            uint32_t pa[4];
            #pragma unroll
            for (int jj = 0; jj < 2; jj++) {
                int j = 2 * kk + jj;
                float2 km2 = *(const float2*)(kms + 8 * j + 2 * t);
                float e0 = km2.x * __expf(s[j][0]);
                float e1 = km2.y * __expf(s[j][1]);
                float e2 = km2.x * __expf(s[j][2]);
                float e3 = km2.y * __expf(s[j][3]);
                uint32_t h01 = packh(e0, e1), h23 = packh(e2, e3);
                pa[2*jj]     = h01;
                pa[2*jj + 1] = h23;
                float2 f01 = unph(h01), f23 = unph(h23);
                rs0 += f01.x + f01.y;         // rounded values -> consistent with MMA2
                rs1 += f23.x + f23.y;
            }
            uint32_t vf[8][2];
            #pragma unroll
            for (int g4 = 0; g4 < 4; g4++) {
                uint32_t a = bV + (uint32_t)((16 * kk) * RST + 32 * g4) + voff;
                LDMX4T(vf[2*g4][0], vf[2*g4][1], vf[2*g4+1][0], vf[2*g4+1][1], a);
            }
            #pragma unroll
            for (int dn = 0; dn < 8; dn++) mma16816h(o[dn], pa, vf[dn]);
        }

        __syncthreads();   // all reads of buf[cur] done
        if (kt + 2 < NKT) {
            prefetch_tile(sb + OFF_T + cur * TILE_SM, tsrc + (size_t)(kt + 2) * TILE_GL, tid);
            if (tid < 128) kms0[cur * 128 + tid] = (float)KM[b * SEQ + (kt + 2) * 128 + tid];
        }
        CP_COMMIT();
    }

    // ---- rowsum reduce within quad ----
    rs0 += __shfl_xor_sync(0xffffffffu, rs0, 1);
    rs0 += __shfl_xor_sync(0xffffffffu, rs0, 2);
    rs1 += __shfl_xor_sync(0xffffffffu, rs1, 1);
    rs1 += __shfl_xor_sync(0xffffffffu, rs1, 2);

    // ---- cross-half reduction (nh=1 stores, nh=0 adds and writes) ----
    float* redo = (float*)(smem + OFF_T);                     // [128][RED_ST]
    float* reds = (float*)(smem + OFF_T + 128 * RED_ST * 4);  // [128]
    __syncthreads();        // tile buffers no longer needed; safe to reuse

    if (nh == 1) {
        #pragma unroll
        for (int dn = 0; dn < 8; dn++) {
            float2 w0; w0.x = o[dn][0]; w0.y = o[dn][1];
            *(float2*)(&redo[(r0 + g) * RED_ST + 8 * dn + 2 * t]) = w0;
            float2 w1; w1.x = o[dn][2]; w1.y = o[dn][3];
            *(float2*)(&redo[(r0 + g + 8) * RED_ST + 8 * dn + 2 * t]) = w1;
        }
        if (t == 0) { reds[r0 + g] = rs0; reds[r0 + g + 8] = rs1; }
    }
    __syncthreads();

    if (nh == 0) {
        const int row0 = q0 + r0 + g, row1 = row0 + 8;
        const float tot0 = rs0 + reds[r0 + g];
        const float tot1 = rs1 + reds[r0 + g + 8];
        const float inv0 = (float)QM[b * SEQ + row0] / fmaxf(tot0, 1.0f);
        const float inv1 = (float)QM[b * SEQ + row1] / fmaxf(tot1, 1.0f);
        float* Ob = O + (size_t)b * SEQ * HD;
        #pragma unroll
        for (int dn = 0; dn < 8; dn++) {
            float2 p0 = *(const float2*)(&redo[(r0 + g) * RED_ST + 8 * dn + 2 * t]);
            float2 p1 = *(const float2*)(&redo[(r0 + g + 8) * RED_ST + 8 * dn + 2 * t]);
            float2 w0; w0.x = (o[dn][0] + p0.x) * inv0; w0.y = (o[dn][1] + p0.y) * inv0;
            *(float2*)(Ob + (size_t)row0 * HD + 8 * dn + 2 * t) = w0;
            float2 w1; w1.x = (o[dn][2] + p1.x) * inv1; w1.y = (o[dn][3] + p1.y) * inv1;
            *(float2*)(Ob + (size_t)row1 * HD + 8 * dn + 2 * t) = w1;
        }
    }
}

extern "C" void kernel_launch(void* const* d_in, const int* in_sizes, int n_in,
                              void* d_out, int out_size)
{
    const float* Q  = (const float*)d_in[0];
    const float* K  = (const float*)d_in[1];
    const float* V  = (const float*)d_in[2];
    const int*   QM = (const int*)d_in[3];
    const int*   KM = (const int*)d_in[4];
    float*       O  = (float*)d_out;

    attn77_prep<<<1536, 256>>>(Q, K, V);

    cudaFuncSetAttribute(attn77_mma, cudaFuncAttributeMaxDynamicSharedMemorySize, SMEM_BYTES);
    attn77_mma<<<128, 512, SMEM_BYTES>>>(QM, KM, O);
}